// round 8
// baseline (speedup 1.0000x reference)
#include <cuda_runtime.h>
#include <cstdint>

typedef unsigned long long ull;

__device__ float  g_xT[8*128*128*64];     // NHWC copy of x
__device__ float4 g_bw[8*128*9*128];      // bilinear corner weights [b][y][k][x]
__device__ unsigned g_bi[8*128*9*128];    // packed lin00 | lin11<<16
__device__ float  g_w[4608];              // deform weights [k][g][cig][o8]

static __device__ __forceinline__ ull pk2(float lo, float hi){
    ull r; asm("mov.b64 %0, {%1, %2};" : "=l"(r) : "f"(lo), "f"(hi)); return r;
}
static __device__ __forceinline__ void unpk2(ull v, float& lo, float& hi){
    asm("mov.b64 {%0, %1}, %2;" : "=f"(lo), "=f"(hi) : "l"(v));
}
static __device__ __forceinline__ ull fma2(ull a, ull b, ull c){
    ull d; asm("fma.rn.f32x2 %0, %1, %2, %3;" : "=l"(d) : "l"(a), "l"(b), "l"(c)); return d;
}

// ---------------------------------------------------------------
// Kernel 1: offset conv 64->18 + bias + PReLU -> bilinear params,
// plus NHWC emit of x, plus (block 0) deform-weight transpose.
// 128 thr = 32x8 px tile, 2 px/thread, chunked channels, 1 bar/chunk.
// ---------------------------------------------------------------
__global__ __launch_bounds__(128) void k_offset(const float* __restrict__ x,
                                                const float* __restrict__ ow,
                                                const float* __restrict__ ob,
                                                const float* __restrict__ pa,
                                                const float* __restrict__ dw)
{
    __shared__ float tile[2][2720];            // [c(8)][r(10)][col(34)]
    __shared__ __align__(16) ull wch[2][720];  // [(c*9+k)][10 ull rows]

    int tid = threadIdx.x;
    int ty = tid >> 4, txq = (tid & 15) * 2;
    int x0 = blockIdx.x*32, y0 = blockIdx.y*8, b = blockIdx.z;

    // block (0,0,0): transpose deform weights for k_deform (overlapped)
    if (blockIdx.x == 0 && blockIdx.y == 0 && blockIdx.z == 0){
        for (int i = tid; i < 4608; i += 128){
            float v = __ldg(&dw[i]);
            int o = i / 72, r = i - o*72;
            int cig = r / 9, k = r - cig*9;
            g_w[((k*8 + (o>>3))*8 + cig)*8 + (o&7)] = v;
        }
    }

    // staging descriptors (chunk-invariant)
    int t_off[22]; unsigned tmask = 0;
#pragma unroll
    for (int s = 0; s < 22; ++s){
        int i = tid + s*128;
        int c = i / 340, rr = i - c*340;
        int r = rr / 34, col = rr - r*34;
        int gy = y0 - 1 + r, gx = x0 - 1 + col;
        t_off[s] = c*16384 + gy*128 + gx;
        if (i < 2720 && (unsigned)gy < 128u && (unsigned)gx < 128u) tmask |= (1u << s);
    }
    int w_src[11], w_dst[11];
#pragma unroll
    for (int s = 0; s < 11; ++s){
        int i = tid + s*128;
        int oc = i / 72, r = i - oc*72;
        w_src[s] = (i < 1296) ? (oc*576 + r) : -1;
        w_dst[s] = r*20 + oc;   // pitch 10 ull = 20 floats
    }
    const float* xb = x + (size_t)b*(64*16384);

    ull acc0[9], acc1[9];
#pragma unroll
    for (int o9 = 0; o9 < 9; ++o9){
        ull b2 = pk2(__ldg(&ob[2*o9]), __ldg(&ob[2*o9+1]));
        acc0[o9] = b2; acc1[o9] = b2;
    }

    // prologue: stage chunk 0 directly
#pragma unroll
    for (int s = 0; s < 11; ++s)
        if (w_src[s] >= 0)
            reinterpret_cast<float*>(wch[0])[w_dst[s]] = __ldg(&ow[w_src[s]]);
#pragma unroll
    for (int s = 0; s < 22; ++s){
        int i = tid + s*128;
        if (i < 2720)
            tile[0][i] = (tmask >> s & 1u) ? __ldg(&xb[t_off[s]]) : 0.f;
    }

    for (int ch = 0; ch < 8; ++ch){
        __syncthreads();
        int bf = ch & 1;
        // prefetch next chunk into registers (hidden under compute)
        float wv[11], tv[22];
        if (ch < 7){
            int c0n = (ch+1)*8;
#pragma unroll
            for (int s = 0; s < 11; ++s)
                wv[s] = (w_src[s] >= 0) ? __ldg(&ow[w_src[s] + c0n*9]) : 0.f;
#pragma unroll
            for (int s = 0; s < 22; ++s)
                tv[s] = (tmask >> s & 1u) ? __ldg(&xb[t_off[s] + c0n*16384]) : 0.f;
        }

        // NHWC emit for this chunk
        int c0 = ch*8;
#pragma unroll
        for (int e = 0; e < 2; ++e){
            int base = (ty+1)*34 + (txq+1+e);
            float4 lo4, hi4;
            lo4.x = tile[bf][0*340+base]; lo4.y = tile[bf][1*340+base];
            lo4.z = tile[bf][2*340+base]; lo4.w = tile[bf][3*340+base];
            hi4.x = tile[bf][4*340+base]; hi4.y = tile[bf][5*340+base];
            hi4.z = tile[bf][6*340+base]; hi4.w = tile[bf][7*340+base];
            float4* dst = reinterpret_cast<float4*>(
                g_xT + ((size_t)(b*128 + y0+ty)*128 + x0+txq+e)*64 + c0);
            dst[0] = lo4; dst[1] = hi4;
        }

        // conv accumulate (2 px share every weight load)
        for (int c = 0; c < 8; ++c){
#pragma unroll
            for (int ky = 0; ky < 3; ++ky){
                int rbase = c*340 + (ty+ky)*34 + txq;
                float2 va = *reinterpret_cast<const float2*>(&tile[bf][rbase]);
                float2 vb = *reinterpret_cast<const float2*>(&tile[bf][rbase+2]);
                float v[4] = {va.x, va.y, vb.x, vb.y};
#pragma unroll
                for (int kx = 0; kx < 3; ++kx){
                    const ulonglong2* wp2 = reinterpret_cast<const ulonglong2*>(
                        &wch[bf][(c*9 + ky*3 + kx)*10]);
                    ulonglong2 w01 = wp2[0], w23 = wp2[1], w45 = wp2[2], w67 = wp2[3];
                    ull w8 = wch[bf][(c*9 + ky*3 + kx)*10 + 8];
                    ull vv0 = pk2(v[kx],   v[kx]);
                    ull vv1 = pk2(v[kx+1], v[kx+1]);
                    acc0[0] = fma2(vv0, w01.x, acc0[0]); acc1[0] = fma2(vv1, w01.x, acc1[0]);
                    acc0[1] = fma2(vv0, w01.y, acc0[1]); acc1[1] = fma2(vv1, w01.y, acc1[1]);
                    acc0[2] = fma2(vv0, w23.x, acc0[2]); acc1[2] = fma2(vv1, w23.x, acc1[2]);
                    acc0[3] = fma2(vv0, w23.y, acc0[3]); acc1[3] = fma2(vv1, w23.y, acc1[3]);
                    acc0[4] = fma2(vv0, w45.x, acc0[4]); acc1[4] = fma2(vv1, w45.x, acc1[4]);
                    acc0[5] = fma2(vv0, w45.y, acc0[5]); acc1[5] = fma2(vv1, w45.y, acc1[5]);
                    acc0[6] = fma2(vv0, w67.x, acc0[6]); acc1[6] = fma2(vv1, w67.x, acc1[6]);
                    acc0[7] = fma2(vv0, w67.y, acc0[7]); acc1[7] = fma2(vv1, w67.y, acc1[7]);
                    acc0[8] = fma2(vv0, w8,    acc0[8]); acc1[8] = fma2(vv1, w8,    acc1[8]);
                }
            }
        }

        // STS next chunk into the other buffers
        if (ch < 7){
            int nb = bf ^ 1;
#pragma unroll
            for (int s = 0; s < 11; ++s)
                if (w_src[s] >= 0)
                    reinterpret_cast<float*>(wch[nb])[w_dst[s]] = wv[s];
#pragma unroll
            for (int s = 0; s < 22; ++s){
                int i = tid + s*128;
                if (i < 2720) tile[nb][i] = tv[s];
            }
        }
    }

    // epilogue: PReLU + bilinear param derivation
    float a = __ldg(&pa[0]);
    int yy = y0 + ty;
#pragma unroll
    for (int e = 0; e < 2; ++e){
        int xx = x0 + txq + e;
#pragma unroll
        for (int k = 0; k < 9; ++k){
            float dy, dx;
            unpk2(e ? acc1[k] : acc0[k], dy, dx);
            dy = dy > 0.f ? dy : a*dy;
            dx = dx > 0.f ? dx : a*dx;
            float py  = (float)yy + (float)(k/3 - 1) + dy;
            float pxx = (float)xx + (float)(k%3 - 1) + dx;
            float y0f = floorf(py), x0f = floorf(pxx);
            float fy = py - y0f, fx = pxx - x0f;
            float vy0 = (y0f >=  0.f && y0f <= 127.f) ? 1.f : 0.f;
            float vy1 = (y0f >= -1.f && y0f <= 126.f) ? 1.f : 0.f;
            float vx0 = (x0f >=  0.f && x0f <= 127.f) ? 1.f : 0.f;
            float vx1 = (x0f >= -1.f && x0f <= 126.f) ? 1.f : 0.f;
            float4 w;
            w.x = (1.f-fy)*(1.f-fx)*vy0*vx0;
            w.y = (1.f-fy)*fx*vy0*vx1;
            w.z = fy*(1.f-fx)*vy1*vx0;
            w.w = fy*fx*vy1*vx1;
            int y0i = (int)y0f, x0i = (int)x0f;
            int yc0 = min(max(y0i,   0), 127), yc1 = min(max(y0i+1, 0), 127);
            int xc0 = min(max(x0i,   0), 127), xc1 = min(max(x0i+1, 0), 127);
            unsigned lin00 = (unsigned)(yc0*128 + xc0);
            unsigned lin11 = (unsigned)(yc1*128 + xc1);
            size_t idx = ((size_t)(b*128 + yy)*9 + k)*128 + xx;
            g_bw[idx] = w;
            g_bi[idx] = lin00 | (lin11 << 16);
        }
    }
}

// ---------------------------------------------------------------
// Kernel 2: deformable grouped conv, pipelined, 17.4 KB smem,
// 8 blocks/SM. Block 128 thr = 32 px of one row.
//  A) warp = 2px x 16 quads: param LDG, coalesced float4 corner
//     gathers, combine, STS.128 (double-buffered, 1 bar/k).
//  B) thread = pixel, warp owns groups 2w,2w+1: warp-uniform __ldg
//     weights from g_w (L1-hot broadcast), private accumulation,
//     direct coalesced STG epilogue.
// ---------------------------------------------------------------
__global__ __launch_bounds__(128, 8) void k_deform(const float* __restrict__ db,
                                                   float* __restrict__ out)
{
    __shared__ __align__(16) float s_buf[2][2176];  // samples [p(32)][68]

    int tid = threadIdx.x;
    int lane = tid & 31, wid = tid >> 5;
    int b = blockIdx.z, y = blockIdx.y, x0 = blockIdx.x*32;

    int q = lane & 15, ph = lane >> 4;    // phase-A identity
    int g0 = wid*2, g1 = wid*2 + 1;       // phase-B identity
    int p = lane;

    const float4* xb = reinterpret_cast<const float4*>(g_xT) + (size_t)b*(128*128*16);
    size_t rowp = ((size_t)(b*128 + y))*9;

    ull acc[8] = {0,0,0,0,0,0,0,0};       // [group(2)][opair(4)]

    auto gather = [&](int kk, float* buf){
        size_t kbase = (rowp + kk)*128;
#pragma unroll
        for (int j = 0; j < 4; ++j){
            int pp = wid*8 + j*2 + ph;
            int xg = x0 + pp;
            float4 w = __ldg(&g_bw[kbase + xg]);
            unsigned bi = __ldg(&g_bi[kbase + xg]);
            int lin00 = bi & 0xFFFFu, lin11 = bi >> 16;
            int xc0 = lin00 & 127, xc1 = lin11 & 127;
            int y0b = lin00 - xc0, y1b = lin11 - xc1;
            float4 c00 = __ldg(&xb[(y0b + xc0)*16 + q]);
            float4 c01 = __ldg(&xb[(y0b + xc1)*16 + q]);
            float4 c10 = __ldg(&xb[(y1b + xc0)*16 + q]);
            float4 c11 = __ldg(&xb[(y1b + xc1)*16 + q]);
            float4 s;
            s.x = w.x*c00.x + w.y*c01.x + w.z*c10.x + w.w*c11.x;
            s.y = w.x*c00.y + w.y*c01.y + w.z*c10.y + w.w*c11.y;
            s.z = w.x*c00.z + w.y*c01.z + w.z*c10.z + w.w*c11.z;
            s.w = w.x*c00.w + w.y*c01.w + w.z*c10.w + w.w*c11.w;
            *reinterpret_cast<float4*>(&buf[pp*68 + 4*q]) = s;
        }
    };

    gather(0, s_buf[0]);

#pragma unroll 1
    for (int k = 0; k < 9; ++k){
        __syncthreads();      // buf[k&1] full; prior gemm reads done
        const float* cur = s_buf[k & 1];
        {
            float4 a0 = *reinterpret_cast<const float4*>(&cur[p*68 + g0*8]);
            float4 a1 = *reinterpret_cast<const float4*>(&cur[p*68 + g0*8 + 4]);
            float4 b0 = *reinterpret_cast<const float4*>(&cur[p*68 + g1*8]);
            float4 b1 = *reinterpret_cast<const float4*>(&cur[p*68 + g1*8 + 4]);
            float sm0[8] = {a0.x,a0.y,a0.z,a0.w, a1.x,a1.y,a1.z,a1.w};
            float sm1[8] = {b0.x,b0.y,b0.z,b0.w, b1.x,b1.y,b1.z,b1.w};
            const ulonglong2* wk0 = reinterpret_cast<const ulonglong2*>(g_w + (k*8 + g0)*64);
            const ulonglong2* wk1 = reinterpret_cast<const ulonglong2*>(g_w + (k*8 + g1)*64);
#pragma unroll
            for (int cig = 0; cig < 8; ++cig){
                ulonglong2 wa = __ldg(&wk0[cig*2]);
                ulonglong2 wb = __ldg(&wk0[cig*2+1]);
                ulonglong2 wc = __ldg(&wk1[cig*2]);
                ulonglong2 wd = __ldg(&wk1[cig*2+1]);
                ull vv0 = pk2(sm0[cig], sm0[cig]);
                ull vv1 = pk2(sm1[cig], sm1[cig]);
                acc[0] = fma2(vv0, wa.x, acc[0]);
                acc[1] = fma2(vv0, wa.y, acc[1]);
                acc[2] = fma2(vv0, wb.x, acc[2]);
                acc[3] = fma2(vv0, wb.y, acc[3]);
                acc[4] = fma2(vv1, wc.x, acc[4]);
                acc[5] = fma2(vv1, wc.y, acc[5]);
                acc[6] = fma2(vv1, wd.x, acc[6]);
                acc[7] = fma2(vv1, wd.y, acc[7]);
            }
        }
        if (k < 8) gather(k+1, s_buf[(k+1) & 1]);
    }

    // epilogue: direct coalesced stores (lane = pixel -> consecutive x)
    float* orow = out + ((size_t)b*64*128 + y)*128 + x0 + p;
#pragma unroll
    for (int gg = 0; gg < 2; ++gg){
        int gb = (gg ? g1 : g0) * 8;
#pragma unroll
        for (int op = 0; op < 4; ++op){
            float lo, hi;
            unpk2(acc[gg*4 + op], lo, hi);
            int o0 = gb + 2*op;
            orow[(size_t)o0*16384]     = lo + __ldg(&db[o0]);
            orow[(size_t)(o0+1)*16384] = hi + __ldg(&db[o0+1]);
        }
    }
}

extern "C" void kernel_launch(void* const* d_in, const int* in_sizes, int n_in,
                              void* d_out, int out_size)
{
    const float* x  = (const float*)d_in[0];
    const float* ow = (const float*)d_in[1];
    const float* ob = (const float*)d_in[2];
    const float* pa = (const float*)d_in[3];
    const float* dw = (const float*)d_in[4];
    const float* db = (const float*)d_in[5];
    float* out = (float*)d_out;

    k_offset<<<dim3(4, 16, 8), 128>>>(x, ow, ob, pa, dw);
    k_deform<<<dim3(4, 128, 8), 128>>>(db, out);
}

// round 9
// speedup vs baseline: 1.2744x; 1.2744x over previous
#include <cuda_runtime.h>
#include <cstdint>

typedef unsigned long long ull;

__device__ float  g_xT[8*128*128*64];     // NHWC copy of x
__device__ float4 g_bw[8*128*9*128];      // bilinear corner weights [b][y][k][x]
__device__ unsigned g_bi[8*128*9*128];    // packed lin00 | lin11<<16
__device__ float  g_w[4608];              // deform weights [k][g][cig][o8]
__constant__ float4 c_w[1152];            // same, as float4 for LDC.128

static __device__ __forceinline__ ull pk2(float lo, float hi){
    ull r; asm("mov.b64 %0, {%1, %2};" : "=l"(r) : "f"(lo), "f"(hi)); return r;
}
static __device__ __forceinline__ void unpk2(ull v, float& lo, float& hi){
    asm("mov.b64 {%0, %1}, %2;" : "=f"(lo), "=f"(hi) : "l"(v));
}
static __device__ __forceinline__ ull fma2(ull a, ull b, ull c){
    ull d; asm("fma.rn.f32x2 %0, %1, %2, %3;" : "=l"(d) : "l"(a), "l"(b), "l"(c)); return d;
}

// ---------------------------------------------------------------
// Kernel 1: offset conv 64->18 + bias + PReLU -> bilinear params,
// plus NHWC emit of x, plus (block 0) deform-weight transpose.
// 128 thr = 32x8 px tile, 2 px/thread, chunked channels, 1 bar/chunk.
// ---------------------------------------------------------------
__global__ __launch_bounds__(128) void k_offset(const float* __restrict__ x,
                                                const float* __restrict__ ow,
                                                const float* __restrict__ ob,
                                                const float* __restrict__ pa,
                                                const float* __restrict__ dw)
{
    __shared__ float tile[2][2720];            // [c(8)][r(10)][col(34)]
    __shared__ __align__(16) ull wch[2][720];  // [(c*9+k)][10 ull rows]

    int tid = threadIdx.x;
    int ty = tid >> 4, txq = (tid & 15) * 2;
    int x0 = blockIdx.x*32, y0 = blockIdx.y*8, b = blockIdx.z;

    // block (0,0,0): transpose deform weights for k_deform (overlapped)
    if (blockIdx.x == 0 && blockIdx.y == 0 && blockIdx.z == 0){
        for (int i = tid; i < 4608; i += 128){
            float v = __ldg(&dw[i]);
            int o = i / 72, r = i - o*72;
            int cig = r / 9, k = r - cig*9;
            g_w[((k*8 + (o>>3))*8 + cig)*8 + (o&7)] = v;
        }
    }

    // staging descriptors (chunk-invariant)
    int t_off[22]; unsigned tmask = 0;
#pragma unroll
    for (int s = 0; s < 22; ++s){
        int i = tid + s*128;
        int c = i / 340, rr = i - c*340;
        int r = rr / 34, col = rr - r*34;
        int gy = y0 - 1 + r, gx = x0 - 1 + col;
        t_off[s] = c*16384 + gy*128 + gx;
        if (i < 2720 && (unsigned)gy < 128u && (unsigned)gx < 128u) tmask |= (1u << s);
    }
    int w_src[11], w_dst[11];
#pragma unroll
    for (int s = 0; s < 11; ++s){
        int i = tid + s*128;
        int oc = i / 72, r = i - oc*72;
        w_src[s] = (i < 1296) ? (oc*576 + r) : -1;
        w_dst[s] = r*20 + oc;   // pitch 10 ull = 20 floats
    }
    const float* xb = x + (size_t)b*(64*16384);

    ull acc0[9], acc1[9];
#pragma unroll
    for (int o9 = 0; o9 < 9; ++o9){
        ull b2 = pk2(__ldg(&ob[2*o9]), __ldg(&ob[2*o9+1]));
        acc0[o9] = b2; acc1[o9] = b2;
    }

    // prologue: stage chunk 0 directly
#pragma unroll
    for (int s = 0; s < 11; ++s)
        if (w_src[s] >= 0)
            reinterpret_cast<float*>(wch[0])[w_dst[s]] = __ldg(&ow[w_src[s]]);
#pragma unroll
    for (int s = 0; s < 22; ++s){
        int i = tid + s*128;
        if (i < 2720)
            tile[0][i] = (tmask >> s & 1u) ? __ldg(&xb[t_off[s]]) : 0.f;
    }

    for (int ch = 0; ch < 8; ++ch){
        __syncthreads();
        int bf = ch & 1;
        // prefetch next chunk into registers (hidden under compute)
        float wv[11], tv[22];
        if (ch < 7){
            int c0n = (ch+1)*8;
#pragma unroll
            for (int s = 0; s < 11; ++s)
                wv[s] = (w_src[s] >= 0) ? __ldg(&ow[w_src[s] + c0n*9]) : 0.f;
#pragma unroll
            for (int s = 0; s < 22; ++s)
                tv[s] = (tmask >> s & 1u) ? __ldg(&xb[t_off[s] + c0n*16384]) : 0.f;
        }

        // NHWC emit for this chunk
        int c0 = ch*8;
#pragma unroll
        for (int e = 0; e < 2; ++e){
            int base = (ty+1)*34 + (txq+1+e);
            float4 lo4, hi4;
            lo4.x = tile[bf][0*340+base]; lo4.y = tile[bf][1*340+base];
            lo4.z = tile[bf][2*340+base]; lo4.w = tile[bf][3*340+base];
            hi4.x = tile[bf][4*340+base]; hi4.y = tile[bf][5*340+base];
            hi4.z = tile[bf][6*340+base]; hi4.w = tile[bf][7*340+base];
            float4* dst = reinterpret_cast<float4*>(
                g_xT + ((size_t)(b*128 + y0+ty)*128 + x0+txq+e)*64 + c0);
            dst[0] = lo4; dst[1] = hi4;
        }

        // conv accumulate (2 px share every weight load)
        for (int c = 0; c < 8; ++c){
#pragma unroll
            for (int ky = 0; ky < 3; ++ky){
                int rbase = c*340 + (ty+ky)*34 + txq;
                float2 va = *reinterpret_cast<const float2*>(&tile[bf][rbase]);
                float2 vb = *reinterpret_cast<const float2*>(&tile[bf][rbase+2]);
                float v[4] = {va.x, va.y, vb.x, vb.y};
#pragma unroll
                for (int kx = 0; kx < 3; ++kx){
                    const ulonglong2* wp2 = reinterpret_cast<const ulonglong2*>(
                        &wch[bf][(c*9 + ky*3 + kx)*10]);
                    ulonglong2 w01 = wp2[0], w23 = wp2[1], w45 = wp2[2], w67 = wp2[3];
                    ull w8 = wch[bf][(c*9 + ky*3 + kx)*10 + 8];
                    ull vv0 = pk2(v[kx],   v[kx]);
                    ull vv1 = pk2(v[kx+1], v[kx+1]);
                    acc0[0] = fma2(vv0, w01.x, acc0[0]); acc1[0] = fma2(vv1, w01.x, acc1[0]);
                    acc0[1] = fma2(vv0, w01.y, acc0[1]); acc1[1] = fma2(vv1, w01.y, acc1[1]);
                    acc0[2] = fma2(vv0, w23.x, acc0[2]); acc1[2] = fma2(vv1, w23.x, acc1[2]);
                    acc0[3] = fma2(vv0, w23.y, acc0[3]); acc1[3] = fma2(vv1, w23.y, acc1[3]);
                    acc0[4] = fma2(vv0, w45.x, acc0[4]); acc1[4] = fma2(vv1, w45.x, acc1[4]);
                    acc0[5] = fma2(vv0, w45.y, acc0[5]); acc1[5] = fma2(vv1, w45.y, acc1[5]);
                    acc0[6] = fma2(vv0, w67.x, acc0[6]); acc1[6] = fma2(vv1, w67.x, acc1[6]);
                    acc0[7] = fma2(vv0, w67.y, acc0[7]); acc1[7] = fma2(vv1, w67.y, acc1[7]);
                    acc0[8] = fma2(vv0, w8,    acc0[8]); acc1[8] = fma2(vv1, w8,    acc1[8]);
                }
            }
        }

        // STS next chunk into the other buffers
        if (ch < 7){
            int nb = bf ^ 1;
#pragma unroll
            for (int s = 0; s < 11; ++s)
                if (w_src[s] >= 0)
                    reinterpret_cast<float*>(wch[nb])[w_dst[s]] = wv[s];
#pragma unroll
            for (int s = 0; s < 22; ++s){
                int i = tid + s*128;
                if (i < 2720) tile[nb][i] = tv[s];
            }
        }
    }

    // epilogue: PReLU + bilinear param derivation
    float a = __ldg(&pa[0]);
    int yy = y0 + ty;
#pragma unroll
    for (int e = 0; e < 2; ++e){
        int xx = x0 + txq + e;
#pragma unroll
        for (int k = 0; k < 9; ++k){
            float dy, dx;
            unpk2(e ? acc1[k] : acc0[k], dy, dx);
            dy = dy > 0.f ? dy : a*dy;
            dx = dx > 0.f ? dx : a*dx;
            float py  = (float)yy + (float)(k/3 - 1) + dy;
            float pxx = (float)xx + (float)(k%3 - 1) + dx;
            float y0f = floorf(py), x0f = floorf(pxx);
            float fy = py - y0f, fx = pxx - x0f;
            float vy0 = (y0f >=  0.f && y0f <= 127.f) ? 1.f : 0.f;
            float vy1 = (y0f >= -1.f && y0f <= 126.f) ? 1.f : 0.f;
            float vx0 = (x0f >=  0.f && x0f <= 127.f) ? 1.f : 0.f;
            float vx1 = (x0f >= -1.f && x0f <= 126.f) ? 1.f : 0.f;
            float4 w;
            w.x = (1.f-fy)*(1.f-fx)*vy0*vx0;
            w.y = (1.f-fy)*fx*vy0*vx1;
            w.z = fy*(1.f-fx)*vy1*vx0;
            w.w = fy*fx*vy1*vx1;
            int y0i = (int)y0f, x0i = (int)x0f;
            int yc0 = min(max(y0i,   0), 127), yc1 = min(max(y0i+1, 0), 127);
            int xc0 = min(max(x0i,   0), 127), xc1 = min(max(x0i+1, 0), 127);
            unsigned lin00 = (unsigned)(yc0*128 + xc0);
            unsigned lin11 = (unsigned)(yc1*128 + xc1);
            size_t idx = ((size_t)(b*128 + yy)*9 + k)*128 + xx;
            g_bw[idx] = w;
            g_bi[idx] = lin00 | (lin11 << 16);
        }
    }
}

// ---------------------------------------------------------------
// Kernel 2: deformable grouped conv. Block 256 thr = 64 px of a row.
// Samples live in smem as [c(64)][p(65 pitch)] (double-buffered,
// 33 KB static, 1 barrier/k):
//  A) warp = 2px x 16 quads (j=0..3): param LDG, coalesced float4
//     corner gathers, combine, 4x STS.32 scatter (2-way max).
//  B) warp = group g=wid, thread -> px (lane, lane+32): stride-1
//     LDS.32 sample reads (conflict-free), weights via LDC.128
//     from __constant__ (zero L1), direct coalesced STG epilogue.
// ---------------------------------------------------------------
__global__ __launch_bounds__(256) void k_deform(const float* __restrict__ db,
                                                float* __restrict__ out)
{
    __shared__ float s_s[2][64*65];   // [c][p] pitch 65

    int tid = threadIdx.x;
    int lane = tid & 31, wid = tid >> 5;
    int b = blockIdx.z, y = blockIdx.y, x0 = blockIdx.x*64;

    int q = lane & 15, ph = lane >> 4;    // phase-A identity
    int g = wid;                          // phase-B identity
    int p0 = lane, p1 = lane + 32;

    const float4* xb = reinterpret_cast<const float4*>(g_xT) + (size_t)b*(128*128*16);
    size_t rowp = ((size_t)(b*128 + y))*9;

    ull acc[8] = {0,0,0,0,0,0,0,0};       // [px(2)][opair(4)]

    auto gather = [&](int kk, float* buf){
        size_t kbase = (rowp + kk)*128;
#pragma unroll
        for (int j = 0; j < 4; ++j){
            int pp = wid*8 + j*2 + ph;
            int xg = x0 + pp;
            float4 w = __ldg(&g_bw[kbase + xg]);
            unsigned bi = __ldg(&g_bi[kbase + xg]);
            int lin00 = bi & 0xFFFFu, lin11 = bi >> 16;
            int xc0 = lin00 & 127, xc1 = lin11 & 127;
            int y0b = lin00 - xc0, y1b = lin11 - xc1;
            float4 c00 = __ldg(&xb[(y0b + xc0)*16 + q]);
            float4 c01 = __ldg(&xb[(y0b + xc1)*16 + q]);
            float4 c10 = __ldg(&xb[(y1b + xc0)*16 + q]);
            float4 c11 = __ldg(&xb[(y1b + xc1)*16 + q]);
            // scatter into [c][p]: rows 4q..4q+3, col pp
            buf[(4*q+0)*65 + pp] = w.x*c00.x + w.y*c01.x + w.z*c10.x + w.w*c11.x;
            buf[(4*q+1)*65 + pp] = w.x*c00.y + w.y*c01.y + w.z*c10.y + w.w*c11.y;
            buf[(4*q+2)*65 + pp] = w.x*c00.z + w.y*c01.z + w.z*c10.z + w.w*c11.z;
            buf[(4*q+3)*65 + pp] = w.x*c00.w + w.y*c01.w + w.z*c10.w + w.w*c11.w;
        }
    };

    gather(0, s_s[0]);

#pragma unroll 1
    for (int k = 0; k < 9; ++k){
        __syncthreads();      // buf[k&1] full; prior gemm reads done
        const float* cur = s_s[k & 1];
        {
            float sm0[8], sm1[8];
#pragma unroll
            for (int cig = 0; cig < 8; ++cig){
                sm0[cig] = cur[(g*8 + cig)*65 + p0];
                sm1[cig] = cur[(g*8 + cig)*65 + p1];
            }
            int wbase = (k*8 + g)*16;     // float4 index into c_w
#pragma unroll
            for (int cig = 0; cig < 8; ++cig){
                float4 wa = c_w[wbase + cig*2];
                float4 wb = c_w[wbase + cig*2 + 1];
                ull w0 = pk2(wa.x, wa.y), w1 = pk2(wa.z, wa.w);
                ull w2 = pk2(wb.x, wb.y), w3 = pk2(wb.z, wb.w);
                ull vv0 = pk2(sm0[cig], sm0[cig]);
                ull vv1 = pk2(sm1[cig], sm1[cig]);
                acc[0] = fma2(vv0, w0, acc[0]);
                acc[1] = fma2(vv0, w1, acc[1]);
                acc[2] = fma2(vv0, w2, acc[2]);
                acc[3] = fma2(vv0, w3, acc[3]);
                acc[4] = fma2(vv1, w0, acc[4]);
                acc[5] = fma2(vv1, w1, acc[5]);
                acc[6] = fma2(vv1, w2, acc[6]);
                acc[7] = fma2(vv1, w3, acc[7]);
            }
        }
        if (k < 8) gather(k+1, s_s[(k+1) & 1]);
    }

    // epilogue: direct coalesced stores (lane = pixel -> consecutive x)
    float* orow = out + ((size_t)b*64*128 + y)*128 + x0;
#pragma unroll
    for (int op = 0; op < 4; ++op){
        int o0 = g*8 + 2*op;
        float b0 = __ldg(&db[o0]), b1 = __ldg(&db[o0+1]);
        float lo, hi;
        unpk2(acc[op], lo, hi);
        orow[(size_t)o0*16384 + p0]     = lo + b0;
        orow[(size_t)(o0+1)*16384 + p0] = hi + b1;
        unpk2(acc[4+op], lo, hi);
        orow[(size_t)o0*16384 + p1]     = lo + b0;
        orow[(size_t)(o0+1)*16384 + p1] = hi + b1;
    }
}

extern "C" void kernel_launch(void* const* d_in, const int* in_sizes, int n_in,
                              void* d_out, int out_size)
{
    const float* x  = (const float*)d_in[0];
    const float* ow = (const float*)d_in[1];
    const float* ob = (const float*)d_in[2];
    const float* pa = (const float*)d_in[3];
    const float* dw = (const float*)d_in[4];
    const float* db = (const float*)d_in[5];
    float* out = (float*)d_out;

    k_offset<<<dim3(4, 16, 8), 128>>>(x, ow, ob, pa, dw);

    // copy transposed weights (g_w, written by k_offset block 0) into
    // __constant__ c_w — D2D async memcpy, graph-capturable
    void* gw_ptr = nullptr;
    cudaGetSymbolAddress(&gw_ptr, g_w);
    cudaMemcpyToSymbolAsync(c_w, gw_ptr, 4608*sizeof(float), 0,
                            cudaMemcpyDeviceToDevice, 0);

    k_deform<<<dim3(2, 128, 8), 256>>>(db, out);
}

// round 10
// speedup vs baseline: 1.3057x; 1.0245x over previous
#include <cuda_runtime.h>
#include <cuda_fp16.h>
#include <cstdint>

typedef unsigned long long ull;

__device__ __half g_xh[8*128*128*64];     // NHWC fp16 copy of x
__device__ float4 g_bw[8*128*9*128];      // bilinear corner weights [b][y][k][x]
__device__ unsigned g_bi[8*128*9*128];    // packed lin00 | lin11<<16
__device__ float  g_w[4608];              // deform weights [k][g][cig][o8]
__constant__ float4 c_w[1152];            // same, as float4 for LDC.128

static __device__ __forceinline__ ull pk2(float lo, float hi){
    ull r; asm("mov.b64 %0, {%1, %2};" : "=l"(r) : "f"(lo), "f"(hi)); return r;
}
static __device__ __forceinline__ void unpk2(ull v, float& lo, float& hi){
    asm("mov.b64 {%0, %1}, %2;" : "=f"(lo), "=f"(hi) : "l"(v));
}
static __device__ __forceinline__ ull fma2(ull a, ull b, ull c){
    ull d; asm("fma.rn.f32x2 %0, %1, %2, %3;" : "=l"(d) : "l"(a), "l"(b), "l"(c)); return d;
}

// ---------------------------------------------------------------
// Kernel 1: offset conv 64->18 + bias + PReLU -> bilinear params,
// plus fp16 NHWC emit of x, plus (block 0) deform-weight transpose.
// 128 thr = 32x8 px tile, 2 px/thread, chunked channels, 1 bar/chunk.
// ---------------------------------------------------------------
__global__ __launch_bounds__(128) void k_offset(const float* __restrict__ x,
                                                const float* __restrict__ ow,
                                                const float* __restrict__ ob,
                                                const float* __restrict__ pa,
                                                const float* __restrict__ dw)
{
    __shared__ float tile[2][2720];            // [c(8)][r(10)][col(34)]
    __shared__ __align__(16) ull wch[2][720];  // [(c*9+k)][10 ull rows]

    int tid = threadIdx.x;
    int ty = tid >> 4, txq = (tid & 15) * 2;
    int x0 = blockIdx.x*32, y0 = blockIdx.y*8, b = blockIdx.z;

    // block (0,0,0): transpose deform weights for k_deform (overlapped)
    if (blockIdx.x == 0 && blockIdx.y == 0 && blockIdx.z == 0){
        for (int i = tid; i < 4608; i += 128){
            float v = __ldg(&dw[i]);
            int o = i / 72, r = i - o*72;
            int cig = r / 9, k = r - cig*9;
            g_w[((k*8 + (o>>3))*8 + cig)*8 + (o&7)] = v;
        }
    }

    // staging descriptors (chunk-invariant)
    int t_off[22]; unsigned tmask = 0;
#pragma unroll
    for (int s = 0; s < 22; ++s){
        int i = tid + s*128;
        int c = i / 340, rr = i - c*340;
        int r = rr / 34, col = rr - r*34;
        int gy = y0 - 1 + r, gx = x0 - 1 + col;
        t_off[s] = c*16384 + gy*128 + gx;
        if (i < 2720 && (unsigned)gy < 128u && (unsigned)gx < 128u) tmask |= (1u << s);
    }
    int w_src[11], w_dst[11];
#pragma unroll
    for (int s = 0; s < 11; ++s){
        int i = tid + s*128;
        int oc = i / 72, r = i - oc*72;
        w_src[s] = (i < 1296) ? (oc*576 + r) : -1;
        w_dst[s] = r*20 + oc;   // pitch 10 ull = 20 floats
    }
    const float* xb = x + (size_t)b*(64*16384);

    ull acc0[9], acc1[9];
#pragma unroll
    for (int o9 = 0; o9 < 9; ++o9){
        ull b2 = pk2(__ldg(&ob[2*o9]), __ldg(&ob[2*o9+1]));
        acc0[o9] = b2; acc1[o9] = b2;
    }

    // prologue: stage chunk 0 directly
#pragma unroll
    for (int s = 0; s < 11; ++s)
        if (w_src[s] >= 0)
            reinterpret_cast<float*>(wch[0])[w_dst[s]] = __ldg(&ow[w_src[s]]);
#pragma unroll
    for (int s = 0; s < 22; ++s){
        int i = tid + s*128;
        if (i < 2720)
            tile[0][i] = (tmask >> s & 1u) ? __ldg(&xb[t_off[s]]) : 0.f;
    }

    for (int ch = 0; ch < 8; ++ch){
        __syncthreads();
        int bf = ch & 1;
        // prefetch next chunk into registers (hidden under compute)
        float wv[11], tv[22];
        if (ch < 7){
            int c0n = (ch+1)*8;
#pragma unroll
            for (int s = 0; s < 11; ++s)
                wv[s] = (w_src[s] >= 0) ? __ldg(&ow[w_src[s] + c0n*9]) : 0.f;
#pragma unroll
            for (int s = 0; s < 22; ++s)
                tv[s] = (tmask >> s & 1u) ? __ldg(&xb[t_off[s] + c0n*16384]) : 0.f;
        }

        // fp16 NHWC emit for this chunk (8 halves = one uint4 store)
        int c0 = ch*8;
#pragma unroll
        for (int e = 0; e < 2; ++e){
            int base = (ty+1)*34 + (txq+1+e);
            __half2 h[4];
            h[0] = __floats2half2_rn(tile[bf][0*340+base], tile[bf][1*340+base]);
            h[1] = __floats2half2_rn(tile[bf][2*340+base], tile[bf][3*340+base]);
            h[2] = __floats2half2_rn(tile[bf][4*340+base], tile[bf][5*340+base]);
            h[3] = __floats2half2_rn(tile[bf][6*340+base], tile[bf][7*340+base]);
            *reinterpret_cast<uint4*>(
                g_xh + ((size_t)(b*128 + y0+ty)*128 + x0+txq+e)*64 + c0)
                = *reinterpret_cast<const uint4*>(h);
        }

        // conv accumulate (2 px share every weight load)
        for (int c = 0; c < 8; ++c){
#pragma unroll
            for (int ky = 0; ky < 3; ++ky){
                int rbase = c*340 + (ty+ky)*34 + txq;
                float2 va = *reinterpret_cast<const float2*>(&tile[bf][rbase]);
                float2 vb = *reinterpret_cast<const float2*>(&tile[bf][rbase+2]);
                float v[4] = {va.x, va.y, vb.x, vb.y};
#pragma unroll
                for (int kx = 0; kx < 3; ++kx){
                    const ulonglong2* wp2 = reinterpret_cast<const ulonglong2*>(
                        &wch[bf][(c*9 + ky*3 + kx)*10]);
                    ulonglong2 w01 = wp2[0], w23 = wp2[1], w45 = wp2[2], w67 = wp2[3];
                    ull w8 = wch[bf][(c*9 + ky*3 + kx)*10 + 8];
                    ull vv0 = pk2(v[kx],   v[kx]);
                    ull vv1 = pk2(v[kx+1], v[kx+1]);
                    acc0[0] = fma2(vv0, w01.x, acc0[0]); acc1[0] = fma2(vv1, w01.x, acc1[0]);
                    acc0[1] = fma2(vv0, w01.y, acc0[1]); acc1[1] = fma2(vv1, w01.y, acc1[1]);
                    acc0[2] = fma2(vv0, w23.x, acc0[2]); acc1[2] = fma2(vv1, w23.x, acc1[2]);
                    acc0[3] = fma2(vv0, w23.y, acc0[3]); acc1[3] = fma2(vv1, w23.y, acc1[3]);
                    acc0[4] = fma2(vv0, w45.x, acc0[4]); acc1[4] = fma2(vv1, w45.x, acc1[4]);
                    acc0[5] = fma2(vv0, w45.y, acc0[5]); acc1[5] = fma2(vv1, w45.y, acc1[5]);
                    acc0[6] = fma2(vv0, w67.x, acc0[6]); acc1[6] = fma2(vv1, w67.x, acc1[6]);
                    acc0[7] = fma2(vv0, w67.y, acc0[7]); acc1[7] = fma2(vv1, w67.y, acc1[7]);
                    acc0[8] = fma2(vv0, w8,    acc0[8]); acc1[8] = fma2(vv1, w8,    acc1[8]);
                }
            }
        }

        // STS next chunk into the other buffers
        if (ch < 7){
            int nb = bf ^ 1;
#pragma unroll
            for (int s = 0; s < 11; ++s)
                if (w_src[s] >= 0)
                    reinterpret_cast<float*>(wch[nb])[w_dst[s]] = wv[s];
#pragma unroll
            for (int s = 0; s < 22; ++s){
                int i = tid + s*128;
                if (i < 2720) tile[nb][i] = tv[s];
            }
        }
    }

    // epilogue: PReLU + bilinear param derivation
    float a = __ldg(&pa[0]);
    int yy = y0 + ty;
#pragma unroll
    for (int e = 0; e < 2; ++e){
        int xx = x0 + txq + e;
#pragma unroll
        for (int k = 0; k < 9; ++k){
            float dy, dx;
            unpk2(e ? acc1[k] : acc0[k], dy, dx);
            dy = dy > 0.f ? dy : a*dy;
            dx = dx > 0.f ? dx : a*dx;
            float py  = (float)yy + (float)(k/3 - 1) + dy;
            float pxx = (float)xx + (float)(k%3 - 1) + dx;
            float y0f = floorf(py), x0f = floorf(pxx);
            float fy = py - y0f, fx = pxx - x0f;
            float vy0 = (y0f >=  0.f && y0f <= 127.f) ? 1.f : 0.f;
            float vy1 = (y0f >= -1.f && y0f <= 126.f) ? 1.f : 0.f;
            float vx0 = (x0f >=  0.f && x0f <= 127.f) ? 1.f : 0.f;
            float vx1 = (x0f >= -1.f && x0f <= 126.f) ? 1.f : 0.f;
            float4 w;
            w.x = (1.f-fy)*(1.f-fx)*vy0*vx0;
            w.y = (1.f-fy)*fx*vy0*vx1;
            w.z = fy*(1.f-fx)*vy1*vx0;
            w.w = fy*fx*vy1*vx1;
            int y0i = (int)y0f, x0i = (int)x0f;
            int yc0 = min(max(y0i,   0), 127), yc1 = min(max(y0i+1, 0), 127);
            int xc0 = min(max(x0i,   0), 127), xc1 = min(max(x0i+1, 0), 127);
            unsigned lin00 = (unsigned)(yc0*128 + xc0);
            unsigned lin11 = (unsigned)(yc1*128 + xc1);
            size_t idx = ((size_t)(b*128 + yy)*9 + k)*128 + xx;
            g_bw[idx] = w;
            g_bi[idx] = lin00 | (lin11 << 16);
        }
    }
}

// ---------------------------------------------------------------
// Kernel 2: deformable grouped conv. Block 256 thr = 64 px of a row.
// fp16 corner gathers (LDG.64: 2 lines/corner vs 4), fp32 combine.
// Samples in smem [c(64)][p(65)] double-buffered, 1 barrier/k.
// Weights from __constant__ (LDC.128, zero L1 traffic).
// ---------------------------------------------------------------
__global__ __launch_bounds__(256) void k_deform(const float* __restrict__ db,
                                                float* __restrict__ out)
{
    __shared__ float s_s[2][64*65];   // [c][p] pitch 65

    int tid = threadIdx.x;
    int lane = tid & 31, wid = tid >> 5;
    int b = blockIdx.z, y = blockIdx.y, x0 = blockIdx.x*64;

    int q = lane & 15, ph = lane >> 4;    // phase-A identity
    int g = wid;                          // phase-B identity
    int p0 = lane, p1 = lane + 32;

    // pixel = 64 halves = 16 uint2; lane q owns channels 4q..4q+3 (one uint2)
    const uint2* xh = reinterpret_cast<const uint2*>(g_xh) + (size_t)b*(128*128*16);
    size_t rowp = ((size_t)(b*128 + y))*9;

    ull acc[8] = {0,0,0,0,0,0,0,0};       // [px(2)][opair(4)]

    auto gather = [&](int kk, float* buf){
        size_t kbase = (rowp + kk)*128;
#pragma unroll
        for (int j = 0; j < 4; ++j){
            int pp = wid*8 + j*2 + ph;
            int xg = x0 + pp;
            float4 w = __ldg(&g_bw[kbase + xg]);
            unsigned bi = __ldg(&g_bi[kbase + xg]);
            int lin00 = bi & 0xFFFFu, lin11 = bi >> 16;
            int xc0 = lin00 & 127, xc1 = lin11 & 127;
            int y0b = lin00 - xc0, y1b = lin11 - xc1;
            uint2 u00 = __ldg(&xh[(y0b + xc0)*16 + q]);
            uint2 u01 = __ldg(&xh[(y0b + xc1)*16 + q]);
            uint2 u10 = __ldg(&xh[(y1b + xc0)*16 + q]);
            uint2 u11 = __ldg(&xh[(y1b + xc1)*16 + q]);
            float2 a00 = __half22float2(*reinterpret_cast<__half2*>(&u00.x));
            float2 b00 = __half22float2(*reinterpret_cast<__half2*>(&u00.y));
            float2 a01 = __half22float2(*reinterpret_cast<__half2*>(&u01.x));
            float2 b01 = __half22float2(*reinterpret_cast<__half2*>(&u01.y));
            float2 a10 = __half22float2(*reinterpret_cast<__half2*>(&u10.x));
            float2 b10 = __half22float2(*reinterpret_cast<__half2*>(&u10.y));
            float2 a11 = __half22float2(*reinterpret_cast<__half2*>(&u11.x));
            float2 b11 = __half22float2(*reinterpret_cast<__half2*>(&u11.y));
            // scatter into [c][p]: rows 4q..4q+3, col pp
            buf[(4*q+0)*65 + pp] = w.x*a00.x + w.y*a01.x + w.z*a10.x + w.w*a11.x;
            buf[(4*q+1)*65 + pp] = w.x*a00.y + w.y*a01.y + w.z*a10.y + w.w*a11.y;
            buf[(4*q+2)*65 + pp] = w.x*b00.x + w.y*b01.x + w.z*b10.x + w.w*b11.x;
            buf[(4*q+3)*65 + pp] = w.x*b00.y + w.y*b01.y + w.z*b10.y + w.w*b11.y;
        }
    };

    gather(0, s_s[0]);

#pragma unroll 1
    for (int k = 0; k < 9; ++k){
        __syncthreads();      // buf[k&1] full; prior gemm reads done
        const float* cur = s_s[k & 1];
        {
            float sm0[8], sm1[8];
#pragma unroll
            for (int cig = 0; cig < 8; ++cig){
                sm0[cig] = cur[(g*8 + cig)*65 + p0];
                sm1[cig] = cur[(g*8 + cig)*65 + p1];
            }
            int wbase = (k*8 + g)*16;     // float4 index into c_w
#pragma unroll
            for (int cig = 0; cig < 8; ++cig){
                float4 wa = c_w[wbase + cig*2];
                float4 wb = c_w[wbase + cig*2 + 1];
                ull w0 = pk2(wa.x, wa.y), w1 = pk2(wa.z, wa.w);
                ull w2 = pk2(wb.x, wb.y), w3 = pk2(wb.z, wb.w);
                ull vv0 = pk2(sm0[cig], sm0[cig]);
                ull vv1 = pk2(sm1[cig], sm1[cig]);
                acc[0] = fma2(vv0, w0, acc[0]);
                acc[1] = fma2(vv0, w1, acc[1]);
                acc[2] = fma2(vv0, w2, acc[2]);
                acc[3] = fma2(vv0, w3, acc[3]);
                acc[4] = fma2(vv1, w0, acc[4]);
                acc[5] = fma2(vv1, w1, acc[5]);
                acc[6] = fma2(vv1, w2, acc[6]);
                acc[7] = fma2(vv1, w3, acc[7]);
            }
        }
        if (k < 8) gather(k+1, s_s[(k+1) & 1]);
    }

    // epilogue: direct coalesced stores (lane = pixel -> consecutive x)
    float* orow = out + ((size_t)b*64*128 + y)*128 + x0;
#pragma unroll
    for (int op = 0; op < 4; ++op){
        int o0 = g*8 + 2*op;
        float b0 = __ldg(&db[o0]), b1 = __ldg(&db[o0+1]);
        float lo, hi;
        unpk2(acc[op], lo, hi);
        orow[(size_t)o0*16384 + p0]     = lo + b0;
        orow[(size_t)(o0+1)*16384 + p0] = hi + b1;
        unpk2(acc[4+op], lo, hi);
        orow[(size_t)o0*16384 + p1]     = lo + b0;
        orow[(size_t)(o0+1)*16384 + p1] = hi + b1;
    }
}

extern "C" void kernel_launch(void* const* d_in, const int* in_sizes, int n_in,
                              void* d_out, int out_size)
{
    const float* x  = (const float*)d_in[0];
    const float* ow = (const float*)d_in[1];
    const float* ob = (const float*)d_in[2];
    const float* pa = (const float*)d_in[3];
    const float* dw = (const float*)d_in[4];
    const float* db = (const float*)d_in[5];
    float* out = (float*)d_out;

    k_offset<<<dim3(4, 16, 8), 128>>>(x, ow, ob, pa, dw);

    // copy transposed weights (g_w, written by k_offset block 0) into
    // __constant__ c_w — D2D async memcpy, graph-capturable
    void* gw_ptr = nullptr;
    cudaGetSymbolAddress(&gw_ptr, g_w);
    cudaMemcpyToSymbolAsync(c_w, gw_ptr, 4608*sizeof(float), 0,
                            cudaMemcpyDeviceToDevice, 0);

    k_deform<<<dim3(2, 128, 8), 256>>>(db, out);
}

// round 11
// speedup vs baseline: 1.3828x; 1.0591x over previous
#include <cuda_runtime.h>
#include <cuda_fp16.h>
#include <cstdint>

typedef unsigned long long ull;

__device__ __half g_xh[8*128*128*64];     // NHWC fp16 copy of x
__device__ float4 g_bw[8*128*9*128];      // bilinear corner weights [b][y][k][x]
__device__ unsigned g_bi[8*128*9*128];    // packed lin00 | lin11<<16
__device__ float  g_w[4608];              // deform weights [k][g][cig][o8]

static __device__ __forceinline__ ull pk2(float lo, float hi){
    ull r; asm("mov.b64 %0, {%1, %2};" : "=l"(r) : "f"(lo), "f"(hi)); return r;
}
static __device__ __forceinline__ void unpk2(ull v, float& lo, float& hi){
    asm("mov.b64 {%0, %1}, %2;" : "=f"(lo), "=f"(hi) : "l"(v));
}
static __device__ __forceinline__ ull fma2(ull a, ull b, ull c){
    ull d; asm("fma.rn.f32x2 %0, %1, %2, %3;" : "=l"(d) : "l"(a), "l"(b), "l"(c)); return d;
}

// ---------------------------------------------------------------
// Kernel 1: offset conv 64->18 + bias + PReLU -> bilinear params,
// plus fp16 NHWC emit of x, plus (block 0) deform-weight transpose.
// 128 thr = 32x8 px tile, 2 px/thread, chunked channels, 1 bar/chunk.
// (Frozen since R8 — passing and ~83 us.)
// ---------------------------------------------------------------
__global__ __launch_bounds__(128) void k_offset(const float* __restrict__ x,
                                                const float* __restrict__ ow,
                                                const float* __restrict__ ob,
                                                const float* __restrict__ pa,
                                                const float* __restrict__ dw)
{
    __shared__ float tile[2][2720];            // [c(8)][r(10)][col(34)]
    __shared__ __align__(16) ull wch[2][720];  // [(c*9+k)][10 ull rows]

    int tid = threadIdx.x;
    int ty = tid >> 4, txq = (tid & 15) * 2;
    int x0 = blockIdx.x*32, y0 = blockIdx.y*8, b = blockIdx.z;

    if (blockIdx.x == 0 && blockIdx.y == 0 && blockIdx.z == 0){
        for (int i = tid; i < 4608; i += 128){
            float v = __ldg(&dw[i]);
            int o = i / 72, r = i - o*72;
            int cig = r / 9, k = r - cig*9;
            g_w[((k*8 + (o>>3))*8 + cig)*8 + (o&7)] = v;
        }
    }

    int t_off[22]; unsigned tmask = 0;
#pragma unroll
    for (int s = 0; s < 22; ++s){
        int i = tid + s*128;
        int c = i / 340, rr = i - c*340;
        int r = rr / 34, col = rr - r*34;
        int gy = y0 - 1 + r, gx = x0 - 1 + col;
        t_off[s] = c*16384 + gy*128 + gx;
        if (i < 2720 && (unsigned)gy < 128u && (unsigned)gx < 128u) tmask |= (1u << s);
    }
    int w_src[11], w_dst[11];
#pragma unroll
    for (int s = 0; s < 11; ++s){
        int i = tid + s*128;
        int oc = i / 72, r = i - oc*72;
        w_src[s] = (i < 1296) ? (oc*576 + r) : -1;
        w_dst[s] = r*20 + oc;
    }
    const float* xb = x + (size_t)b*(64*16384);

    ull acc0[9], acc1[9];
#pragma unroll
    for (int o9 = 0; o9 < 9; ++o9){
        ull b2 = pk2(__ldg(&ob[2*o9]), __ldg(&ob[2*o9+1]));
        acc0[o9] = b2; acc1[o9] = b2;
    }

#pragma unroll
    for (int s = 0; s < 11; ++s)
        if (w_src[s] >= 0)
            reinterpret_cast<float*>(wch[0])[w_dst[s]] = __ldg(&ow[w_src[s]]);
#pragma unroll
    for (int s = 0; s < 22; ++s){
        int i = tid + s*128;
        if (i < 2720)
            tile[0][i] = (tmask >> s & 1u) ? __ldg(&xb[t_off[s]]) : 0.f;
    }

    for (int ch = 0; ch < 8; ++ch){
        __syncthreads();
        int bf = ch & 1;
        float wv[11], tv[22];
        if (ch < 7){
            int c0n = (ch+1)*8;
#pragma unroll
            for (int s = 0; s < 11; ++s)
                wv[s] = (w_src[s] >= 0) ? __ldg(&ow[w_src[s] + c0n*9]) : 0.f;
#pragma unroll
            for (int s = 0; s < 22; ++s)
                tv[s] = (tmask >> s & 1u) ? __ldg(&xb[t_off[s] + c0n*16384]) : 0.f;
        }

        int c0 = ch*8;
#pragma unroll
        for (int e = 0; e < 2; ++e){
            int base = (ty+1)*34 + (txq+1+e);
            __half2 h[4];
            h[0] = __floats2half2_rn(tile[bf][0*340+base], tile[bf][1*340+base]);
            h[1] = __floats2half2_rn(tile[bf][2*340+base], tile[bf][3*340+base]);
            h[2] = __floats2half2_rn(tile[bf][4*340+base], tile[bf][5*340+base]);
            h[3] = __floats2half2_rn(tile[bf][6*340+base], tile[bf][7*340+base]);
            *reinterpret_cast<uint4*>(
                g_xh + ((size_t)(b*128 + y0+ty)*128 + x0+txq+e)*64 + c0)
                = *reinterpret_cast<const uint4*>(h);
        }

        for (int c = 0; c < 8; ++c){
#pragma unroll
            for (int ky = 0; ky < 3; ++ky){
                int rbase = c*340 + (ty+ky)*34 + txq;
                float2 va = *reinterpret_cast<const float2*>(&tile[bf][rbase]);
                float2 vb = *reinterpret_cast<const float2*>(&tile[bf][rbase+2]);
                float v[4] = {va.x, va.y, vb.x, vb.y};
#pragma unroll
                for (int kx = 0; kx < 3; ++kx){
                    const ulonglong2* wp2 = reinterpret_cast<const ulonglong2*>(
                        &wch[bf][(c*9 + ky*3 + kx)*10]);
                    ulonglong2 w01 = wp2[0], w23 = wp2[1], w45 = wp2[2], w67 = wp2[3];
                    ull w8 = wch[bf][(c*9 + ky*3 + kx)*10 + 8];
                    ull vv0 = pk2(v[kx],   v[kx]);
                    ull vv1 = pk2(v[kx+1], v[kx+1]);
                    acc0[0] = fma2(vv0, w01.x, acc0[0]); acc1[0] = fma2(vv1, w01.x, acc1[0]);
                    acc0[1] = fma2(vv0, w01.y, acc0[1]); acc1[1] = fma2(vv1, w01.y, acc1[1]);
                    acc0[2] = fma2(vv0, w23.x, acc0[2]); acc1[2] = fma2(vv1, w23.x, acc1[2]);
                    acc0[3] = fma2(vv0, w23.y, acc0[3]); acc1[3] = fma2(vv1, w23.y, acc1[3]);
                    acc0[4] = fma2(vv0, w45.x, acc0[4]); acc1[4] = fma2(vv1, w45.x, acc1[4]);
                    acc0[5] = fma2(vv0, w45.y, acc0[5]); acc1[5] = fma2(vv1, w45.y, acc1[5]);
                    acc0[6] = fma2(vv0, w67.x, acc0[6]); acc1[6] = fma2(vv1, w67.x, acc1[6]);
                    acc0[7] = fma2(vv0, w67.y, acc0[7]); acc1[7] = fma2(vv1, w67.y, acc1[7]);
                    acc0[8] = fma2(vv0, w8,    acc0[8]); acc1[8] = fma2(vv1, w8,    acc1[8]);
                }
            }
        }

        if (ch < 7){
            int nb = bf ^ 1;
#pragma unroll
            for (int s = 0; s < 11; ++s)
                if (w_src[s] >= 0)
                    reinterpret_cast<float*>(wch[nb])[w_dst[s]] = wv[s];
#pragma unroll
            for (int s = 0; s < 22; ++s){
                int i = tid + s*128;
                if (i < 2720) tile[nb][i] = tv[s];
            }
        }
    }

    float a = __ldg(&pa[0]);
    int yy = y0 + ty;
#pragma unroll
    for (int e = 0; e < 2; ++e){
        int xx = x0 + txq + e;
#pragma unroll
        for (int k = 0; k < 9; ++k){
            float dy, dx;
            unpk2(e ? acc1[k] : acc0[k], dy, dx);
            dy = dy > 0.f ? dy : a*dy;
            dx = dx > 0.f ? dx : a*dx;
            float py  = (float)yy + (float)(k/3 - 1) + dy;
            float pxx = (float)xx + (float)(k%3 - 1) + dx;
            float y0f = floorf(py), x0f = floorf(pxx);
            float fy = py - y0f, fx = pxx - x0f;
            float vy0 = (y0f >=  0.f && y0f <= 127.f) ? 1.f : 0.f;
            float vy1 = (y0f >= -1.f && y0f <= 126.f) ? 1.f : 0.f;
            float vx0 = (x0f >=  0.f && x0f <= 127.f) ? 1.f : 0.f;
            float vx1 = (x0f >= -1.f && x0f <= 126.f) ? 1.f : 0.f;
            float4 w;
            w.x = (1.f-fy)*(1.f-fx)*vy0*vx0;
            w.y = (1.f-fy)*fx*vy0*vx1;
            w.z = fy*(1.f-fx)*vy1*vx0;
            w.w = fy*fx*vy1*vx1;
            int y0i = (int)y0f, x0i = (int)x0f;
            int yc0 = min(max(y0i,   0), 127), yc1 = min(max(y0i+1, 0), 127);
            int xc0 = min(max(x0i,   0), 127), xc1 = min(max(x0i+1, 0), 127);
            unsigned lin00 = (unsigned)(yc0*128 + xc0);
            unsigned lin11 = (unsigned)(yc1*128 + xc1);
            size_t idx = ((size_t)(b*128 + yy)*9 + k)*128 + xx;
            g_bw[idx] = w;
            g_bi[idx] = lin00 | (lin11 << 16);
        }
    }
}

// ---------------------------------------------------------------
// Kernel 2: deformable grouped conv. Block 256 thr = 64 px of a row.
// fp16 corner gathers; fp16 sample smem [c2(32)][p(66)] (half2 of
// channel pairs), double-buffered + smem weights = 35 KB, 1 bar/k.
//  A) warp = 2px x 16 quads: param LDG, 4 LDG.64 corners, fp32
//     combine, 2x STS.32 (half2).
//  B) warp = group g, thread -> px (lane, lane+32): 8 LDS.32 half2
//     samples + cvt, broadcast LDS.128 weights, direct STG epilogue.
// ---------------------------------------------------------------
__global__ __launch_bounds__(256) void k_deform(const float* __restrict__ db,
                                                float* __restrict__ out)
{
    __shared__ __align__(16) float s_w[4608];        // [k][g][cig][o8]
    __shared__ __align__(16) __half2 s_h[2][32*66];  // [c2][p] pitch 66

    int tid = threadIdx.x;
    int lane = tid & 31, wid = tid >> 5;
    int b = blockIdx.z, y = blockIdx.y, x0 = blockIdx.x*64;

    // stage pre-transposed weights (coalesced; g_w written by k_offset blk 0)
    for (int i = tid; i < 4608; i += 256) s_w[i] = g_w[i];

    int q = lane & 15, ph = lane >> 4;    // phase-A identity
    int g = wid;                          // phase-B identity
    int p0 = lane, p1 = lane + 32;

    const uint2* xh = reinterpret_cast<const uint2*>(g_xh) + (size_t)b*(128*128*16);
    size_t rowp = ((size_t)(b*128 + y))*9;

    ull acc[8] = {0,0,0,0,0,0,0,0};       // [px(2)][opair(4)]

    auto gather = [&](int kk, __half2* buf){
        size_t kbase = (rowp + kk)*128;
#pragma unroll
        for (int j = 0; j < 4; ++j){
            int pp = wid*8 + j*2 + ph;
            int xg = x0 + pp;
            float4 w = __ldg(&g_bw[kbase + xg]);
            unsigned bi = __ldg(&g_bi[kbase + xg]);
            int lin00 = bi & 0xFFFFu, lin11 = bi >> 16;
            int xc0 = lin00 & 127, xc1 = lin11 & 127;
            int y0b = lin00 - xc0, y1b = lin11 - xc1;
            uint2 u00 = __ldg(&xh[(y0b + xc0)*16 + q]);
            uint2 u01 = __ldg(&xh[(y0b + xc1)*16 + q]);
            uint2 u10 = __ldg(&xh[(y1b + xc0)*16 + q]);
            uint2 u11 = __ldg(&xh[(y1b + xc1)*16 + q]);
            float2 a00 = __half22float2(*reinterpret_cast<__half2*>(&u00.x));
            float2 b00 = __half22float2(*reinterpret_cast<__half2*>(&u00.y));
            float2 a01 = __half22float2(*reinterpret_cast<__half2*>(&u01.x));
            float2 b01 = __half22float2(*reinterpret_cast<__half2*>(&u01.y));
            float2 a10 = __half22float2(*reinterpret_cast<__half2*>(&u10.x));
            float2 b10 = __half22float2(*reinterpret_cast<__half2*>(&u10.y));
            float2 a11 = __half22float2(*reinterpret_cast<__half2*>(&u11.x));
            float2 b11 = __half22float2(*reinterpret_cast<__half2*>(&u11.y));
            float s0 = w.x*a00.x + w.y*a01.x + w.z*a10.x + w.w*a11.x;
            float s1 = w.x*a00.y + w.y*a01.y + w.z*a10.y + w.w*a11.y;
            float s2 = w.x*b00.x + w.y*b01.x + w.z*b10.x + w.w*b11.x;
            float s3 = w.x*b00.y + w.y*b01.y + w.z*b10.y + w.w*b11.y;
            buf[(2*q+0)*66 + pp] = __floats2half2_rn(s0, s1);
            buf[(2*q+1)*66 + pp] = __floats2half2_rn(s2, s3);
        }
    };

    gather(0, s_h[0]);

#pragma unroll 1
    for (int k = 0; k < 9; ++k){
        __syncthreads();      // weights + buf[k&1] ready; prior gemm reads done
        const __half2* cur = s_h[k & 1];
        {
            float2 f0[4], f1[4];
#pragma unroll
            for (int i = 0; i < 4; ++i){
                f0[i] = __half22float2(cur[(g*4 + i)*66 + p0]);
                f1[i] = __half22float2(cur[(g*4 + i)*66 + p1]);
            }
            float sm0[8] = {f0[0].x,f0[0].y,f0[1].x,f0[1].y,f0[2].x,f0[2].y,f0[3].x,f0[3].y};
            float sm1[8] = {f1[0].x,f1[0].y,f1[1].x,f1[1].y,f1[2].x,f1[2].y,f1[3].x,f1[3].y};
            const ulonglong2* wk = reinterpret_cast<const ulonglong2*>(&s_w[(k*8 + g)*64]);
#pragma unroll
            for (int cig = 0; cig < 8; ++cig){
                ulonglong2 wab = wk[cig*2];
                ulonglong2 wcd = wk[cig*2+1];
                ull vv0 = pk2(sm0[cig], sm0[cig]);
                ull vv1 = pk2(sm1[cig], sm1[cig]);
                acc[0] = fma2(vv0, wab.x, acc[0]);
                acc[1] = fma2(vv0, wab.y, acc[1]);
                acc[2] = fma2(vv0, wcd.x, acc[2]);
                acc[3] = fma2(vv0, wcd.y, acc[3]);
                acc[4] = fma2(vv1, wab.x, acc[4]);
                acc[5] = fma2(vv1, wab.y, acc[5]);
                acc[6] = fma2(vv1, wcd.x, acc[6]);
                acc[7] = fma2(vv1, wcd.y, acc[7]);
            }
        }
        if (k < 8) gather(k+1, s_h[(k+1) & 1]);
    }

    // epilogue: direct coalesced stores (lane = pixel -> consecutive x)
    float* orow = out + ((size_t)b*64*128 + y)*128 + x0;
#pragma unroll
    for (int op = 0; op < 4; ++op){
        int o0 = g*8 + 2*op;
        float b0 = __ldg(&db[o0]), b1 = __ldg(&db[o0+1]);
        float lo, hi;
        unpk2(acc[op], lo, hi);
        orow[(size_t)o0*16384 + p0]     = lo + b0;
        orow[(size_t)(o0+1)*16384 + p0] = hi + b1;
        unpk2(acc[4+op], lo, hi);
        orow[(size_t)o0*16384 + p1]     = lo + b0;
        orow[(size_t)(o0+1)*16384 + p1] = hi + b1;
    }
}

extern "C" void kernel_launch(void* const* d_in, const int* in_sizes, int n_in,
                              void* d_out, int out_size)
{
    const float* x  = (const float*)d_in[0];
    const float* ow = (const float*)d_in[1];
    const float* ob = (const float*)d_in[2];
    const float* pa = (const float*)d_in[3];
    const float* dw = (const float*)d_in[4];
    const float* db = (const float*)d_in[5];
    float* out = (float*)d_out;

    k_offset<<<dim3(4, 16, 8), 128>>>(x, ow, ob, pa, dw);
    k_deform<<<dim3(2, 128, 8), 256>>>(db, out);
}